// round 1
// baseline (speedup 1.0000x reference)
#include <cuda_runtime.h>
#include <cstdint>
#include <cstddef>
#include <math.h>

// Problem constants
#define B_   8
#define NQ_  1024
#define NKV_ 1024
#define DQ_  512
#define DKV_ 512
#define H_   8
#define DH_  64
#define BH_  64   // B*H

// Scratch (static __device__ arrays — allocation-free per harness rules)
__device__ float g_Qp[BH_ * NQ_ * DH_];       // [bh, q, d]
__device__ float g_Kp[BH_ * NKV_ * DH_];      // [bh, k, d]
__device__ float g_Vp[BH_ * NKV_ * DH_];      // [bh, k, d]
__device__ float g_Obuf[B_ * NQ_ * H_ * DH_]; // [b, q, h*64+d]
__device__ float g_attn_scratch[(size_t)BH_ * NQ_ * NKV_]; // fallback if attn not in d_out

// ---------------------------------------------------------------------------
// Generic SGEMM: C = A[M,K] @ W[K,N] + bias.  128x128 tile, BK=8, 8x8 microtile.
// qkv_layout=1 scatters output into [bh, n, 64] layout.
// ---------------------------------------------------------------------------
__global__ __launch_bounds__(256) void sgemm_kernel(
    const float* __restrict__ A, const float* __restrict__ W,
    const float* __restrict__ bias, float* __restrict__ C,
    int M, int N, int K, int qkv_layout)
{
    __shared__ float As[8][132];
    __shared__ float Bs[8][132];
    int tid = threadIdx.x;
    int tx = tid & 15, ty = tid >> 4;
    int m0 = blockIdx.y * 128, n0 = blockIdx.x * 128;
    float acc[8][8] = {};
    int a_row = tid >> 1, a_col = (tid & 1) * 4;
    int b_row = tid >> 5, b_col = (tid & 31) * 4;
    for (int k0 = 0; k0 < K; k0 += 8) {
        float4 av = *(const float4*)(A + (size_t)(m0 + a_row) * K + k0 + a_col);
        As[a_col + 0][a_row] = av.x; As[a_col + 1][a_row] = av.y;
        As[a_col + 2][a_row] = av.z; As[a_col + 3][a_row] = av.w;
        float4 bv = *(const float4*)(W + (size_t)(k0 + b_row) * N + n0 + b_col);
        *(float4*)&Bs[b_row][b_col] = bv;
        __syncthreads();
#pragma unroll
        for (int kk = 0; kk < 8; kk++) {
            float a[8], b[8];
            *(float4*)(a)     = *(float4*)&As[kk][ty * 8];
            *(float4*)(a + 4) = *(float4*)&As[kk][ty * 8 + 4];
            *(float4*)(b)     = *(float4*)&Bs[kk][tx * 8];
            *(float4*)(b + 4) = *(float4*)&Bs[kk][tx * 8 + 4];
#pragma unroll
            for (int i = 0; i < 8; i++)
#pragma unroll
                for (int j = 0; j < 8; j++)
                    acc[i][j] += a[i] * b[j];
        }
        __syncthreads();
    }
#pragma unroll
    for (int i = 0; i < 8; i++) {
        int m = m0 + ty * 8 + i;
#pragma unroll
        for (int j = 0; j < 8; j++) {
            int n = n0 + tx * 8 + j;
            float v = acc[i][j] + bias[n];
            if (qkv_layout) {
                int bb = m >> 10, ns = m & 1023, h = n >> 6, d = n & 63;
                C[((size_t)((bb * 8 + h) * 1024 + ns)) * 64 + d] = v;
            } else {
                C[(size_t)m * N + n] = v;
            }
        }
    }
}

// ---------------------------------------------------------------------------
// RPE bias GEMM: for fixed q, scores[bh, k] = sum_d Q[bh,q,d] * R[q,k,d].
// Grid: (kc=8, q=1024). R[q] tile loaded once, reused across all 64 bh.
// Writes raw scores into attn buffer (QK^T kernel accumulates on top).
// ---------------------------------------------------------------------------
__global__ __launch_bounds__(256) void rpe_kernel(
    const float* __restrict__ Qp, const float* __restrict__ R,
    float* __restrict__ attn)
{
    __shared__ float Qs[32][68];   // [d][bh]
    __shared__ float Rs[32][132];  // [d][k]
    int q  = blockIdx.y;
    int k0 = blockIdx.x * 128;
    int tid = threadIdx.x;
    int tx = tid & 15, ty = tid >> 4;
    float acc[4][8] = {};
    for (int dk = 0; dk < 64; dk += 32) {
#pragma unroll
        for (int l = 0; l < 2; l++) {
            int f = tid + l * 256;
            int row = f >> 3;          // bh 0..63
            int col = (f & 7) * 4;     // d 0..28
            float4 v = *(const float4*)(Qp + ((size_t)row * 1024 + q) * 64 + dk + col);
            Qs[col + 0][row] = v.x; Qs[col + 1][row] = v.y;
            Qs[col + 2][row] = v.z; Qs[col + 3][row] = v.w;
        }
#pragma unroll
        for (int l = 0; l < 4; l++) {
            int f = tid + l * 256;
            int row = f >> 3;          // k 0..127
            int col = (f & 7) * 4;
            float4 v = *(const float4*)(R + ((size_t)q * 1024 + k0 + row) * 64 + dk + col);
            Rs[col + 0][row] = v.x; Rs[col + 1][row] = v.y;
            Rs[col + 2][row] = v.z; Rs[col + 3][row] = v.w;
        }
        __syncthreads();
#pragma unroll
        for (int d = 0; d < 32; d++) {
            float a[4], b[8];
            *(float4*)(a)     = *(float4*)&Qs[d][ty * 4];
            *(float4*)(b)     = *(float4*)&Rs[d][tx * 8];
            *(float4*)(b + 4) = *(float4*)&Rs[d][tx * 8 + 4];
#pragma unroll
            for (int i = 0; i < 4; i++)
#pragma unroll
                for (int j = 0; j < 8; j++)
                    acc[i][j] += a[i] * b[j];
        }
        __syncthreads();
    }
#pragma unroll
    for (int i = 0; i < 4; i++) {
        int bh = ty * 4 + i;
        float* dst = attn + ((size_t)bh * 1024 + q) * 1024 + k0 + tx * 8;
        *(float4*)(dst)     = *(float4*)&acc[i][0];
        *(float4*)(dst + 4) = *(float4*)&acc[i][4];
    }
}

// ---------------------------------------------------------------------------
// QK^T batched GEMM: attn[bh, q, k] += sum_d Q[bh,q,d]*K[bh,k,d].
// Grid: (kt=8, qt=8, bh=64). 128x128 tile, BK=16.
// ---------------------------------------------------------------------------
__global__ __launch_bounds__(256) void qk_kernel(
    const float* __restrict__ Qp, const float* __restrict__ Kp,
    float* __restrict__ attn)
{
    __shared__ float As[16][132];
    __shared__ float Bs[16][132];
    int bh = blockIdx.z;
    int m0 = blockIdx.y * 128, n0 = blockIdx.x * 128;
    const float* Aq = Qp + (size_t)bh * NQ_ * DH_;
    const float* Bk = Kp + (size_t)bh * NKV_ * DH_;
    int tid = threadIdx.x;
    int tx = tid & 15, ty = tid >> 4;
    float acc[8][8] = {};
    for (int k0 = 0; k0 < 64; k0 += 16) {
#pragma unroll
        for (int l = 0; l < 2; l++) {
            int f = tid + l * 256;
            int row = f >> 2;          // 0..127
            int col = (f & 3) * 4;     // 0..12
            float4 av = *(const float4*)(Aq + (size_t)(m0 + row) * 64 + k0 + col);
            As[col + 0][row] = av.x; As[col + 1][row] = av.y;
            As[col + 2][row] = av.z; As[col + 3][row] = av.w;
            float4 bv = *(const float4*)(Bk + (size_t)(n0 + row) * 64 + k0 + col);
            Bs[col + 0][row] = bv.x; Bs[col + 1][row] = bv.y;
            Bs[col + 2][row] = bv.z; Bs[col + 3][row] = bv.w;
        }
        __syncthreads();
#pragma unroll
        for (int kk = 0; kk < 16; kk++) {
            float a[8], b[8];
            *(float4*)(a)     = *(float4*)&As[kk][ty * 8];
            *(float4*)(a + 4) = *(float4*)&As[kk][ty * 8 + 4];
            *(float4*)(b)     = *(float4*)&Bs[kk][tx * 8];
            *(float4*)(b + 4) = *(float4*)&Bs[kk][tx * 8 + 4];
#pragma unroll
            for (int i = 0; i < 8; i++)
#pragma unroll
                for (int j = 0; j < 8; j++)
                    acc[i][j] += a[i] * b[j];
        }
        __syncthreads();
    }
    float* C = attn + ((size_t)bh << 20);
#pragma unroll
    for (int i = 0; i < 8; i++) {
        int m = m0 + ty * 8 + i;
        float* p = C + (size_t)m * 1024 + n0 + tx * 8;
        float4 c0 = *(float4*)p, c1 = *(float4*)(p + 4);
        c0.x += acc[i][0]; c0.y += acc[i][1]; c0.z += acc[i][2]; c0.w += acc[i][3];
        c1.x += acc[i][4]; c1.y += acc[i][5]; c1.z += acc[i][6]; c1.w += acc[i][7];
        *(float4*)p = c0; *(float4*)(p + 4) = c1;
    }
}

// ---------------------------------------------------------------------------
// Row softmax with scale + mask.  One block per (bh, q) row of 1024.
// ---------------------------------------------------------------------------
__global__ __launch_bounds__(256) void softmax_kernel(
    float* __restrict__ attn, const int* __restrict__ mask)
{
    size_t row = blockIdx.x;
    int bh = (int)(row >> 10);
    int b  = bh >> 3;
    float* x = attn + row * 1024;
    const int4* mr = (const int4*)(mask + b * 1024);
    int tid = threadIdx.x;
    float4 v = ((float4*)x)[tid];
    int4 m = mr[tid];
    const float scale = 0.125f;  // DH^-0.5
    v.x = m.x ? v.x * scale : -INFINITY;
    v.y = m.y ? v.y * scale : -INFINITY;
    v.z = m.z ? v.z * scale : -INFINITY;
    v.w = m.w ? v.w * scale : -INFINITY;
    float mx = fmaxf(fmaxf(v.x, v.y), fmaxf(v.z, v.w));
#pragma unroll
    for (int o = 16; o; o >>= 1) mx = fmaxf(mx, __shfl_xor_sync(0xffffffffu, mx, o));
    __shared__ float redm[8];
    __shared__ float reds[8];
    if ((tid & 31) == 0) redm[tid >> 5] = mx;
    __syncthreads();
    mx = redm[0];
#pragma unroll
    for (int w = 1; w < 8; w++) mx = fmaxf(mx, redm[w]);
    v.x = __expf(v.x - mx); v.y = __expf(v.y - mx);
    v.z = __expf(v.z - mx); v.w = __expf(v.w - mx);
    float s = v.x + v.y + v.z + v.w;
#pragma unroll
    for (int o = 16; o; o >>= 1) s += __shfl_xor_sync(0xffffffffu, s, o);
    if ((tid & 31) == 0) reds[tid >> 5] = s;
    __syncthreads();
    s = reds[0];
#pragma unroll
    for (int w = 1; w < 8; w++) s += reds[w];
    float inv = 1.0f / s;
    v.x *= inv; v.y *= inv; v.z *= inv; v.w *= inv;
    ((float4*)x)[tid] = v;
}

// ---------------------------------------------------------------------------
// AV batched GEMM: O[bh, q, d] = sum_k P[bh,q,k]*V[bh,k,d], scattered into
// Obuf layout [b, q, h*64+d].  Grid: (qt=8, bh=64). 128x64 tile, BK=16.
// ---------------------------------------------------------------------------
__global__ __launch_bounds__(256) void av_kernel(
    const float* __restrict__ attn, const float* __restrict__ Vp,
    float* __restrict__ Obuf)
{
    __shared__ float As[16][132];
    __shared__ float Bs[16][68];
    int bh = blockIdx.y;
    int b = bh >> 3, h = bh & 7;
    int m0 = blockIdx.x * 128;
    const float* P = attn + ((size_t)bh << 20);
    const float* V = Vp + (size_t)bh * NKV_ * DH_;
    int tid = threadIdx.x;
    int tx = tid & 15, ty = tid >> 4;
    float acc[8][4] = {};
    for (int k0 = 0; k0 < 1024; k0 += 16) {
#pragma unroll
        for (int l = 0; l < 2; l++) {
            int f = tid + l * 256;
            int row = f >> 2;
            int col = (f & 3) * 4;
            float4 av = *(const float4*)(P + (size_t)(m0 + row) * 1024 + k0 + col);
            As[col + 0][row] = av.x; As[col + 1][row] = av.y;
            As[col + 2][row] = av.z; As[col + 3][row] = av.w;
        }
        {
            int row = tid >> 4;
            int col = (tid & 15) * 4;
            *(float4*)&Bs[row][col] = *(const float4*)(V + (size_t)(k0 + row) * 64 + col);
        }
        __syncthreads();
#pragma unroll
        for (int kk = 0; kk < 16; kk++) {
            float a[8], bb[4];
            *(float4*)(a)     = *(float4*)&As[kk][ty * 8];
            *(float4*)(a + 4) = *(float4*)&As[kk][ty * 8 + 4];
            *(float4*)(bb)    = *(float4*)&Bs[kk][tx * 4];
#pragma unroll
            for (int i = 0; i < 8; i++)
#pragma unroll
                for (int j = 0; j < 4; j++)
                    acc[i][j] += a[i] * bb[j];
        }
        __syncthreads();
    }
#pragma unroll
    for (int i = 0; i < 8; i++) {
        int q = m0 + ty * 8 + i;
        float* dst = Obuf + ((size_t)(b * 1024 + q)) * 512 + h * 64 + tx * 4;
        *(float4*)dst = *(float4*)&acc[i][0];
    }
}

// ---------------------------------------------------------------------------
extern "C" void kernel_launch(void* const* d_in, const int* in_sizes, int n_in,
                              void* d_out, int out_size)
{
    const float* q    = (const float*)d_in[0];
    const float* kv   = (const float*)d_in[1];
    const int*   mask = (const int*)d_in[2];
    const float* Wq   = (const float*)d_in[3];
    const float* bq   = (const float*)d_in[4];
    const float* Wk   = (const float*)d_in[5];
    const float* bk   = (const float*)d_in[6];
    const float* Wv   = (const float*)d_in[7];
    const float* bv   = (const float*)d_in[8];
    const float* Wo   = (const float*)d_in[9];
    const float* bo   = (const float*)d_in[10];
    const float* R    = (const float*)d_in[11];

    float* out = (float*)d_out;
    const size_t OUT0_ELEMS = (size_t)B_ * NQ_ * DQ_;            // 4,194,304
    const size_t ATTN_ELEMS = (size_t)BH_ * NQ_ * NKV_;          // 67,108,864

    float *Qp, *Kp, *Vp, *Ob, *attn_scr;
    cudaGetSymbolAddress((void**)&Qp, g_Qp);
    cudaGetSymbolAddress((void**)&Kp, g_Kp);
    cudaGetSymbolAddress((void**)&Vp, g_Vp);
    cudaGetSymbolAddress((void**)&Ob, g_Obuf);
    cudaGetSymbolAddress((void**)&attn_scr, g_attn_scratch);

    // Reference returns (out, attn); harness output is the flattened concat.
    float* attn = ((size_t)out_size >= OUT0_ELEMS + ATTN_ELEMS) ? (out + OUT0_ELEMS)
                                                                : attn_scr;

    dim3 gP(512 / 128, (B_ * NQ_) / 128);   // (4, 64)

    // Projections -> [bh, n, 64] layout
    sgemm_kernel<<<gP, 256>>>(q,  Wq, bq, Qp, B_ * NQ_,  H_ * DH_, DQ_,  1);
    sgemm_kernel<<<gP, 256>>>(kv, Wk, bk, Kp, B_ * NKV_, H_ * DH_, DKV_, 1);
    sgemm_kernel<<<gP, 256>>>(kv, Wv, bv, Vp, B_ * NKV_, H_ * DH_, DKV_, 1);

    // RPE bias writes raw scores; QK^T accumulates on top
    rpe_kernel<<<dim3(NKV_ / 128, NQ_), 256>>>(Qp, R, attn);
    qk_kernel<<<dim3(NKV_ / 128, NQ_ / 128, BH_), 256>>>(Qp, Kp, attn);

    // scale + mask + softmax (in place)
    softmax_kernel<<<BH_ * NQ_, 256>>>(attn, mask);

    // attn @ V -> Obuf [b, q, h*64+d]
    av_kernel<<<dim3(NQ_ / 128, BH_), 256>>>(attn, Vp, Ob);

    // final projection -> out
    sgemm_kernel<<<gP, 256>>>(Ob, Wo, bo, out, B_ * NQ_, DQ_, H_ * DH_, 0);
}

// round 2
// speedup vs baseline: 1.7687x; 1.7687x over previous
#include <cuda_runtime.h>
#include <cstdint>
#include <cstddef>
#include <math.h>

// Problem constants
#define B_   8
#define NQ_  1024
#define NKV_ 1024
#define DQ_  512
#define H_   8
#define DH_  64
#define BH_  64

// Scratch (static __device__ arrays — allocation-free per harness rules)
__device__ float g_Qp[BH_ * NQ_ * DH_];       // [bh, q, d]
__device__ float g_Kp[BH_ * NKV_ * DH_];      // [bh, k, d]
__device__ float g_Vp[BH_ * NKV_ * DH_];      // [bh, k, d]
__device__ float g_Obuf[B_ * NQ_ * H_ * DH_]; // [b, q, h*64+d]
__device__ float g_attn_scratch[(size_t)BH_ * NQ_ * NKV_];

__device__ __forceinline__ uint32_t f2tf(float f) {
    uint32_t u; asm("cvt.rna.tf32.f32 %0, %1;" : "=r"(u) : "f"(f)); return u;
}

__device__ __forceinline__ void mma8(float* c, const uint32_t* a, const uint32_t* b) {
    asm volatile(
        "mma.sync.aligned.m16n8k8.row.col.f32.tf32.tf32.f32 "
        "{%0,%1,%2,%3},{%4,%5,%6,%7},{%8,%9},{%0,%1,%2,%3};"
        : "+f"(c[0]), "+f"(c[1]), "+f"(c[2]), "+f"(c[3])
        : "r"(a[0]), "r"(a[1]), "r"(a[2]), "r"(a[3]), "r"(b[0]), "r"(b[1]));
}

// ---------------------------------------------------------------------------
// Generic batched GEMM on tf32 tensor cores with split-tf32 (3-MMA) accuracy.
//   C[m,n] (+)= sum_k A[m,k] * B[.,.]     A: gmem row-major via lda
//   BCOL=true : B source is [N,K] row-major (ldb = K-row stride)  (K, R)
//   BCOL=false: B source is [K,N] row-major                        (W, V)
// EPI: 0 = plain store (+bias if non-null), 1 = QKV scatter (+bias),
//      2 = RMW add into C, 3 = AV scatter into Obuf [b,q,h*64+d]
// ---------------------------------------------------------------------------
template <int BM, int BN, int BK, int WM, int WN, bool BCOL, int EPI>
__global__ __launch_bounds__(256, 1) void mma_gemm(
    const float* __restrict__ A, const float* __restrict__ Bg,
    const float* __restrict__ bias, float* __restrict__ C,
    int K, long lda, long ldb, long ldc, long sA, long sB, long sC)
{
    constexpr int MT = WM / 16, NT = WN / 8;
    constexpr int WX = BN / WN;
    constexpr int BR = BCOL ? BN : BK;          // Bs rows
    constexpr int BCW = BCOL ? (BK + 4) : (BN + 8);  // Bs row width (u32)

    __shared__ uint32_t sAh[BM][BK + 4], sAl[BM][BK + 4];
    __shared__ uint32_t sBh[BR][BCW],    sBl[BR][BCW];

    const int tid = threadIdx.x;
    const int warp = tid >> 5, lane = tid & 31;
    const int wx = warp % WX, wy = warp / WX;
    const long z = blockIdx.z;

    const float* Ab = A + z * sA + (long)blockIdx.y * BM * lda;
    const float* Bb = BCOL ? (Bg + z * sB + (long)blockIdx.x * BN * ldb)
                           : (Bg + z * sB + (long)blockIdx.x * BN);

    float acc[MT * NT][4];
#pragma unroll
    for (int i = 0; i < MT * NT; i++)
#pragma unroll
        for (int r = 0; r < 4; r++) acc[i][r] = 0.0f;

    for (int k0 = 0; k0 < K; k0 += BK) {
        // ---- stage A tile (convert to tf32 hi/lo) ----
        constexpr int AIT = (BM * BK / 4) / 256;
#pragma unroll
        for (int it = 0; it < AIT; it++) {
            int idx = tid + it * 256;
            int m = idx / (BK / 4), k4 = (idx % (BK / 4)) * 4;
            float4 v = *(const float4*)(Ab + (long)m * lda + k0 + k4);
            uint32_t h0 = f2tf(v.x), h1 = f2tf(v.y), h2 = f2tf(v.z), h3 = f2tf(v.w);
            sAh[m][k4 + 0] = h0; sAh[m][k4 + 1] = h1;
            sAh[m][k4 + 2] = h2; sAh[m][k4 + 3] = h3;
            sAl[m][k4 + 0] = f2tf(v.x - __uint_as_float(h0));
            sAl[m][k4 + 1] = f2tf(v.y - __uint_as_float(h1));
            sAl[m][k4 + 2] = f2tf(v.z - __uint_as_float(h2));
            sAl[m][k4 + 3] = f2tf(v.w - __uint_as_float(h3));
        }
        // ---- stage B tile ----
        if (BCOL) {
            constexpr int BIT = (BN * BK / 4) / 256;
#pragma unroll
            for (int it = 0; it < BIT; it++) {
                int idx = tid + it * 256;
                int n = idx / (BK / 4), k4 = (idx % (BK / 4)) * 4;
                float4 v = *(const float4*)(Bb + (long)n * ldb + k0 + k4);
                uint32_t h0 = f2tf(v.x), h1 = f2tf(v.y), h2 = f2tf(v.z), h3 = f2tf(v.w);
                sBh[n][k4 + 0] = h0; sBh[n][k4 + 1] = h1;
                sBh[n][k4 + 2] = h2; sBh[n][k4 + 3] = h3;
                sBl[n][k4 + 0] = f2tf(v.x - __uint_as_float(h0));
                sBl[n][k4 + 1] = f2tf(v.y - __uint_as_float(h1));
                sBl[n][k4 + 2] = f2tf(v.z - __uint_as_float(h2));
                sBl[n][k4 + 3] = f2tf(v.w - __uint_as_float(h3));
            }
        } else {
            constexpr int BIT = (BK * BN / 4) / 256;
#pragma unroll
            for (int it = 0; it < BIT; it++) {
                int idx = tid + it * 256;
                int k = idx / (BN / 4), n4 = (idx % (BN / 4)) * 4;
                float4 v = *(const float4*)(Bb + (long)(k0 + k) * ldb + n4);
                uint32_t h0 = f2tf(v.x), h1 = f2tf(v.y), h2 = f2tf(v.z), h3 = f2tf(v.w);
                sBh[k][n4 + 0] = h0; sBh[k][n4 + 1] = h1;
                sBh[k][n4 + 2] = h2; sBh[k][n4 + 3] = h3;
                sBl[k][n4 + 0] = f2tf(v.x - __uint_as_float(h0));
                sBl[k][n4 + 1] = f2tf(v.y - __uint_as_float(h1));
                sBl[k][n4 + 2] = f2tf(v.z - __uint_as_float(h2));
                sBl[k][n4 + 3] = f2tf(v.w - __uint_as_float(h3));
            }
        }
        __syncthreads();

        // ---- compute ----
#pragma unroll
        for (int kk = 0; kk < BK; kk += 8) {
            uint32_t afh[MT][4], afl[MT][4];
            const int kb = kk + (lane & 3);
            const int mrow = wy * WM + (lane >> 2);
#pragma unroll
            for (int i = 0; i < MT; i++) {
                int m = mrow + i * 16;
                afh[i][0] = sAh[m][kb];     afh[i][1] = sAh[m + 8][kb];
                afh[i][2] = sAh[m][kb + 4]; afh[i][3] = sAh[m + 8][kb + 4];
                afl[i][0] = sAl[m][kb];     afl[i][1] = sAl[m + 8][kb];
                afl[i][2] = sAl[m][kb + 4]; afl[i][3] = sAl[m + 8][kb + 4];
            }
#pragma unroll
            for (int j = 0; j < NT; j++) {
                uint32_t bfh[2], bfl[2];
                int n = wx * WN + j * 8 + (lane >> 2);
                if (BCOL) {
                    bfh[0] = sBh[n][kb]; bfh[1] = sBh[n][kb + 4];
                    bfl[0] = sBl[n][kb]; bfl[1] = sBl[n][kb + 4];
                } else {
                    bfh[0] = sBh[kb][n]; bfh[1] = sBh[kb + 4][n];
                    bfl[0] = sBl[kb][n]; bfl[1] = sBl[kb + 4][n];
                }
#pragma unroll
                for (int i = 0; i < MT; i++) {
                    mma8(acc[i * NT + j], afh[i], bfh);
                    mma8(acc[i * NT + j], afh[i], bfl);
                    mma8(acc[i * NT + j], afl[i], bfh);
                }
            }
        }
        __syncthreads();
    }

    // ---- epilogue ----
    const long m0 = (long)blockIdx.y * BM + wy * WM;
    const long n0 = (long)blockIdx.x * BN + wx * WN;
    float* Cb = C + z * sC;
    long ldcc = ldc;
    if (EPI == 3) { Cb = C + (z >> 3) * 524288 + (z & 7) * 64; ldcc = 512; }

#pragma unroll
    for (int i = 0; i < MT; i++) {
#pragma unroll
        for (int j = 0; j < NT; j++) {
#pragma unroll
            for (int r2 = 0; r2 < 2; r2++) {
                long row = m0 + i * 16 + r2 * 8 + (lane >> 2);
                long col = n0 + j * 8 + (lane & 3) * 2;
                float v0 = acc[i * NT + j][r2 * 2 + 0];
                float v1 = acc[i * NT + j][r2 * 2 + 1];
                if ((EPI == 0 || EPI == 1) && bias) { v0 += bias[col]; v1 += bias[col + 1]; }
                if (EPI == 1) {
                    long bb = row >> 10, ns = row & 1023;
                    long h = col >> 6, d = col & 63;
                    float* p = C + (((bb * 8 + h) * 1024 + ns) * 64 + d);
                    *(float2*)p = make_float2(v0, v1);
                } else if (EPI == 2) {
                    float2* p = (float2*)(Cb + row * ldcc + col);
                    float2 o = *p; o.x += v0; o.y += v1; *p = o;
                } else {
                    *(float2*)(Cb + row * ldcc + col) = make_float2(v0, v1);
                }
            }
        }
    }
}

// ---------------------------------------------------------------------------
// Row softmax with scale + mask.  One block per (bh, q) row of 1024.
// ---------------------------------------------------------------------------
__global__ __launch_bounds__(256) void softmax_kernel(
    float* __restrict__ attn, const int* __restrict__ mask)
{
    size_t row = blockIdx.x;
    int bh = (int)(row >> 10);
    int b  = bh >> 3;
    float* x = attn + row * 1024;
    const int4* mr = (const int4*)(mask + b * 1024);
    int tid = threadIdx.x;
    float4 v = ((float4*)x)[tid];
    int4 m = mr[tid];
    const float scale = 0.125f;  // DH^-0.5
    v.x = m.x ? v.x * scale : -INFINITY;
    v.y = m.y ? v.y * scale : -INFINITY;
    v.z = m.z ? v.z * scale : -INFINITY;
    v.w = m.w ? v.w * scale : -INFINITY;
    float mx = fmaxf(fmaxf(v.x, v.y), fmaxf(v.z, v.w));
#pragma unroll
    for (int o = 16; o; o >>= 1) mx = fmaxf(mx, __shfl_xor_sync(0xffffffffu, mx, o));
    __shared__ float redm[8];
    __shared__ float reds[8];
    if ((tid & 31) == 0) redm[tid >> 5] = mx;
    __syncthreads();
    mx = redm[0];
#pragma unroll
    for (int w = 1; w < 8; w++) mx = fmaxf(mx, redm[w]);
    v.x = __expf(v.x - mx); v.y = __expf(v.y - mx);
    v.z = __expf(v.z - mx); v.w = __expf(v.w - mx);
    float s = v.x + v.y + v.z + v.w;
#pragma unroll
    for (int o = 16; o; o >>= 1) s += __shfl_xor_sync(0xffffffffu, s, o);
    if ((tid & 31) == 0) reds[tid >> 5] = s;
    __syncthreads();
    s = reds[0];
#pragma unroll
    for (int w = 1; w < 8; w++) s += reds[w];
    float inv = 1.0f / s;
    v.x *= inv; v.y *= inv; v.z *= inv; v.w *= inv;
    ((float4*)x)[tid] = v;
}

// ---------------------------------------------------------------------------
extern "C" void kernel_launch(void* const* d_in, const int* in_sizes, int n_in,
                              void* d_out, int out_size)
{
    const float* q    = (const float*)d_in[0];
    const float* kv   = (const float*)d_in[1];
    const int*   mask = (const int*)d_in[2];
    const float* Wq   = (const float*)d_in[3];
    const float* bq   = (const float*)d_in[4];
    const float* Wk   = (const float*)d_in[5];
    const float* bk   = (const float*)d_in[6];
    const float* Wv   = (const float*)d_in[7];
    const float* bv   = (const float*)d_in[8];
    const float* Wo   = (const float*)d_in[9];
    const float* bo   = (const float*)d_in[10];
    const float* R    = (const float*)d_in[11];

    float* out = (float*)d_out;
    const size_t OUT0_ELEMS = (size_t)B_ * NQ_ * DQ_;
    const size_t ATTN_ELEMS = (size_t)BH_ * NQ_ * NKV_;

    float *Qp, *Kp, *Vp, *Ob, *attn_scr;
    cudaGetSymbolAddress((void**)&Qp, g_Qp);
    cudaGetSymbolAddress((void**)&Kp, g_Kp);
    cudaGetSymbolAddress((void**)&Vp, g_Vp);
    cudaGetSymbolAddress((void**)&Ob, g_Obuf);
    cudaGetSymbolAddress((void**)&attn_scr, g_attn_scratch);

    float* attn = ((size_t)out_size >= OUT0_ELEMS + ATTN_ELEMS) ? (out + OUT0_ELEMS)
                                                                : attn_scr;

    // Projections: [8192,512] @ [512,512] -> scatter [bh, n, 64]
    mma_gemm<128,128,16,64,32,false,1><<<dim3(4,64,1),256>>>(
        q,  Wq, bq, Qp, 512, 512, 512, 0, 0, 0, 0);
    mma_gemm<128,128,16,64,32,false,1><<<dim3(4,64,1),256>>>(
        kv, Wk, bk, Kp, 512, 512, 512, 0, 0, 0, 0);
    mma_gemm<128,128,16,64,32,false,1><<<dim3(4,64,1),256>>>(
        kv, Wv, bv, Vp, 512, 512, 512, 0, 0, 0, 0);

    // RPE: per-q [64bh x 64d] @ R[q]^T[64d x 1024k] -> raw scores
    mma_gemm<64,128,16,32,32,true,0><<<dim3(8,1,1024),256>>>(
        Qp, R, nullptr, attn, 64,
        /*lda=*/65536, /*ldb=*/64, /*ldc=*/1048576,
        /*sA=*/64, /*sB=*/65536, /*sC=*/1024);

    // QK^T: batched [1024 x 64] @ K^T -> RMW into scores
    mma_gemm<128,128,16,64,32,true,2><<<dim3(8,8,64),256>>>(
        Qp, Kp, nullptr, attn, 64,
        /*lda=*/64, /*ldb=*/64, /*ldc=*/1024,
        /*sA=*/65536, /*sB=*/65536, /*sC=*/1048576);

    // scale + mask + softmax (in place)
    softmax_kernel<<<BH_ * NQ_, 256>>>(attn, mask);

    // AV: batched [1024 x 1024] @ V[1024 x 64] -> Obuf [b,q,h*64+d]
    mma_gemm<128,64,16,32,32,false,3><<<dim3(1,8,64),256>>>(
        attn, Vp, nullptr, Ob, 1024,
        /*lda=*/1024, /*ldb=*/64, /*ldc=*/0,
        /*sA=*/1048576, /*sB=*/65536, /*sC=*/0);

    // Out projection: [8192,512] @ [512,512] -> out
    mma_gemm<128,128,16,64,32,false,0><<<dim3(4,64,1),256>>>(
        Ob, Wo, bo, out, 512, 512, 512, 512, 0, 0, 0);
}

// round 4
// speedup vs baseline: 2.5947x; 1.4670x over previous
#include <cuda_runtime.h>
#include <cstdint>
#include <cstddef>
#include <math.h>

#define B_   8
#define NQ_  1024
#define NKV_ 1024
#define DQ_  512
#define H_   8
#define DH_  64
#define BH_  64

__device__ float g_Qp[BH_ * NQ_ * DH_];       // [bh, q, d]
__device__ float g_Kp[BH_ * NKV_ * DH_];      // [bh, k, d]
__device__ float g_Vp[BH_ * NKV_ * DH_];      // [bh, k, d]
__device__ float g_Obuf[B_ * NQ_ * H_ * DH_]; // [b, q, h*64+d]
__device__ float g_attn_scratch[(size_t)BH_ * NQ_ * NKV_];

// pack two floats into bf16x2: x0 -> low half, x1 -> high half
__device__ __forceinline__ uint32_t packbf(float x0, float x1) {
    uint32_t r;
    asm("cvt.rn.bf16x2.f32 %0, %1, %2;" : "=r"(r) : "f"(x1), "f"(x0));
    return r;
}
__device__ __forceinline__ float bf_lo(uint32_t r) { return __uint_as_float(r << 16); }
__device__ __forceinline__ float bf_hi(uint32_t r) { return __uint_as_float(r & 0xffff0000u); }

__device__ __forceinline__ void mma16(float* c, const uint32_t* a, const uint32_t* b) {
    asm volatile(
        "mma.sync.aligned.m16n8k16.row.col.f32.bf16.bf16.f32 "
        "{%0,%1,%2,%3},{%4,%5,%6,%7},{%8,%9},{%0,%1,%2,%3};"
        : "+f"(c[0]), "+f"(c[1]), "+f"(c[2]), "+f"(c[3])
        : "r"(a[0]), "r"(a[1]), "r"(a[2]), "r"(a[3]), "r"(b[0]), "r"(b[1]));
}

// ---------------------------------------------------------------------------
// Batched GEMM on bf16 tensor cores with split-bf16 accuracy.
//   C[m,n] (+)= sum_k A[m,k]*B[..]   A row-major via lda.
//   BCOL=true : B source [N,K] row-major.  BCOL=false: B source [K,N].
// NSPLIT: 3 = hi*hi + hi*lo + lo*hi (≈fp32), 1 = plain bf16.
// EPI: 0 store(+bias), 1 QKV scatter(+bias), 2 RMW add, 3 AV scatter.
// Smem words pack bf16 pairs along k; fragment index math matches m16n8k16.
// ---------------------------------------------------------------------------
template <int BM, int BN, int BK, int WM, int WN, bool BCOL, int EPI, int NSPLIT>
__global__ __launch_bounds__(256, 1) void mma_gemm(
    const float* __restrict__ A, const float* __restrict__ Bg,
    const float* __restrict__ bias, float* __restrict__ C,
    int K, long lda, long ldb, long ldc, long sA, long sB, long sC)
{
    constexpr int MT = WM / 16, NT = WN / 8;
    constexpr int WX = BN / WN;
    constexpr int KW = BK / 2;                 // k-pair words per row
    constexpr bool SPL = (NSPLIT == 3);
    constexpr int BR  = BCOL ? BN : KW;        // Bs rows
    constexpr int BCW = BCOL ? (KW + 4) : (BN + 8);

    __shared__ uint32_t sAh[BM][KW + 4];
    __shared__ uint32_t sAl[SPL ? BM : 1][SPL ? KW + 4 : 1];
    __shared__ uint32_t sBh[BR][BCW];
    __shared__ uint32_t sBl[SPL ? BR : 1][SPL ? BCW : 1];

    const int tid = threadIdx.x;
    const int warp = tid >> 5, lane = tid & 31;
    const int wx = warp % WX, wy = warp / WX;
    const long z = blockIdx.z;

    const float* Ab = A + z * sA + (long)blockIdx.y * BM * lda;
    const float* Bb = BCOL ? (Bg + z * sB + (long)blockIdx.x * BN * ldb)
                           : (Bg + z * sB + (long)blockIdx.x * BN);

    float acc[MT * NT][4];
#pragma unroll
    for (int i = 0; i < MT * NT; i++)
#pragma unroll
        for (int r = 0; r < 4; r++) acc[i][r] = 0.0f;

    for (int k0 = 0; k0 < K; k0 += BK) {
        // ---- stage A ----
        constexpr int AIT = (BM * BK / 4) / 256;
#pragma unroll
        for (int it = 0; it < AIT; it++) {
            int idx = tid + it * 256;
            int m = idx / (BK / 4), kq = idx % (BK / 4);
            float4 v = *(const float4*)(Ab + (long)m * lda + k0 + kq * 4);
            uint32_t h0 = packbf(v.x, v.y), h1 = packbf(v.z, v.w);
            sAh[m][kq * 2] = h0; sAh[m][kq * 2 + 1] = h1;
            if (SPL) {
                sAl[m][kq * 2]     = packbf(v.x - bf_lo(h0), v.y - bf_hi(h0));
                sAl[m][kq * 2 + 1] = packbf(v.z - bf_lo(h1), v.w - bf_hi(h1));
            }
        }
        // ---- stage B ----
        if (BCOL) {
            constexpr int BIT = (BN * BK / 4) / 256;
#pragma unroll
            for (int it = 0; it < BIT; it++) {
                int idx = tid + it * 256;
                int n = idx / (BK / 4), kq = idx % (BK / 4);
                float4 v = *(const float4*)(Bb + (long)n * ldb + k0 + kq * 4);
                uint32_t h0 = packbf(v.x, v.y), h1 = packbf(v.z, v.w);
                sBh[n][kq * 2] = h0; sBh[n][kq * 2 + 1] = h1;
                if (SPL) {
                    sBl[n][kq * 2]     = packbf(v.x - bf_lo(h0), v.y - bf_hi(h0));
                    sBl[n][kq * 2 + 1] = packbf(v.z - bf_lo(h1), v.w - bf_hi(h1));
                }
            }
        } else {
            constexpr int BIT = (KW * (BN / 4) + 255) / 256;
#pragma unroll
            for (int it = 0; it < BIT; it++) {
                int idx = tid + it * 256;
                if (KW * (BN / 4) % 256 != 0 && idx >= KW * (BN / 4)) break;
                int kp = idx / (BN / 4), n4 = (idx % (BN / 4)) * 4;
                float4 v0 = *(const float4*)(Bb + (long)(k0 + kp * 2) * ldb + n4);
                float4 v1 = *(const float4*)(Bb + (long)(k0 + kp * 2 + 1) * ldb + n4);
                uint32_t h0 = packbf(v0.x, v1.x), h1 = packbf(v0.y, v1.y);
                uint32_t h2 = packbf(v0.z, v1.z), h3 = packbf(v0.w, v1.w);
                sBh[kp][n4 + 0] = h0; sBh[kp][n4 + 1] = h1;
                sBh[kp][n4 + 2] = h2; sBh[kp][n4 + 3] = h3;
                if (SPL) {
                    sBl[kp][n4 + 0] = packbf(v0.x - bf_lo(h0), v1.x - bf_hi(h0));
                    sBl[kp][n4 + 1] = packbf(v0.y - bf_lo(h1), v1.y - bf_hi(h1));
                    sBl[kp][n4 + 2] = packbf(v0.z - bf_lo(h2), v1.z - bf_hi(h2));
                    sBl[kp][n4 + 3] = packbf(v0.w - bf_lo(h3), v1.w - bf_hi(h3));
                }
            }
        }
        __syncthreads();

        // ---- compute: one m16n8k16 triple (or single) per k16 chunk ----
#pragma unroll
        for (int kc = 0; kc < KW; kc += 8) {
            const int kb = kc + (lane & 3);
            const int mrow = wy * WM + (lane >> 2);
            uint32_t afh[MT][4], afl[MT][4];
#pragma unroll
            for (int i = 0; i < MT; i++) {
                int m = mrow + i * 16;
                afh[i][0] = sAh[m][kb];     afh[i][1] = sAh[m + 8][kb];
                afh[i][2] = sAh[m][kb + 4]; afh[i][3] = sAh[m + 8][kb + 4];
                if (SPL) {
                    afl[i][0] = sAl[m][kb];     afl[i][1] = sAl[m + 8][kb];
                    afl[i][2] = sAl[m][kb + 4]; afl[i][3] = sAl[m + 8][kb + 4];
                }
            }
#pragma unroll
            for (int j = 0; j < NT; j++) {
                uint32_t bfh[2], bfl[2];
                int n = wx * WN + j * 8 + (lane >> 2);
                if (BCOL) {
                    bfh[0] = sBh[n][kb]; bfh[1] = sBh[n][kb + 4];
                    if (SPL) { bfl[0] = sBl[n][kb]; bfl[1] = sBl[n][kb + 4]; }
                } else {
                    bfh[0] = sBh[kb][n]; bfh[1] = sBh[kb + 4][n];
                    if (SPL) { bfl[0] = sBl[kb][n]; bfl[1] = sBl[kb + 4][n]; }
                }
#pragma unroll
                for (int i = 0; i < MT; i++) {
                    mma16(acc[i * NT + j], afh[i], bfh);
                    if (SPL) {
                        mma16(acc[i * NT + j], afh[i], bfl);
                        mma16(acc[i * NT + j], afl[i], bfh);
                    }
                }
            }
        }
        __syncthreads();
    }

    // ---- epilogue ----
    const long m0 = (long)blockIdx.y * BM + wy * WM;
    const long n0 = (long)blockIdx.x * BN + wx * WN;
    float* Cb = C + z * sC;
    long ldcc = ldc;
    if (EPI == 3) { Cb = C + (z >> 3) * 524288 + (z & 7) * 64; ldcc = 512; }

#pragma unroll
    for (int i = 0; i < MT; i++) {
#pragma unroll
        for (int j = 0; j < NT; j++) {
#pragma unroll
            for (int r2 = 0; r2 < 2; r2++) {
                long row = m0 + i * 16 + r2 * 8 + (lane >> 2);
                long col = n0 + j * 8 + (lane & 3) * 2;
                float v0 = acc[i * NT + j][r2 * 2 + 0];
                float v1 = acc[i * NT + j][r2 * 2 + 1];
                if ((EPI == 0 || EPI == 1) && bias) { v0 += bias[col]; v1 += bias[col + 1]; }
                if (EPI == 1) {
                    long bb = row >> 10, ns = row & 1023;
                    long h = col >> 6, d = col & 63;
                    float* p = C + (((bb * 8 + h) * 1024 + ns) * 64 + d);
                    *(float2*)p = make_float2(v0, v1);
                } else if (EPI == 2) {
                    float2* p = (float2*)(Cb + row * ldcc + col);
                    float2 o = *p; o.x += v0; o.y += v1; *p = o;
                } else {
                    *(float2*)(Cb + row * ldcc + col) = make_float2(v0, v1);
                }
            }
        }
    }
}

// ---------------------------------------------------------------------------
// Row softmax with scale + mask.  One block per (bh, q) row of 1024.
// ---------------------------------------------------------------------------
__global__ __launch_bounds__(256) void softmax_kernel(
    float* __restrict__ attn, const int* __restrict__ mask)
{
    size_t row = blockIdx.x;
    int bh = (int)(row >> 10);
    int b  = bh >> 3;
    float* x = attn + row * 1024;
    const int4* mr = (const int4*)(mask + b * 1024);
    int tid = threadIdx.x;
    float4 v = ((float4*)x)[tid];
    int4 m = mr[tid];
    const float scale = 0.125f;
    v.x = m.x ? v.x * scale : -INFINITY;
    v.y = m.y ? v.y * scale : -INFINITY;
    v.z = m.z ? v.z * scale : -INFINITY;
    v.w = m.w ? v.w * scale : -INFINITY;
    float mx = fmaxf(fmaxf(v.x, v.y), fmaxf(v.z, v.w));
#pragma unroll
    for (int o = 16; o; o >>= 1) mx = fmaxf(mx, __shfl_xor_sync(0xffffffffu, mx, o));
    __shared__ float redm[8];
    __shared__ float reds[8];
    if ((tid & 31) == 0) redm[tid >> 5] = mx;
    __syncthreads();
    mx = redm[0];
#pragma unroll
    for (int w = 1; w < 8; w++) mx = fmaxf(mx, redm[w]);
    v.x = __expf(v.x - mx); v.y = __expf(v.y - mx);
    v.z = __expf(v.z - mx); v.w = __expf(v.w - mx);
    float s = v.x + v.y + v.z + v.w;
#pragma unroll
    for (int o = 16; o; o >>= 1) s += __shfl_xor_sync(0xffffffffu, s, o);
    if ((tid & 31) == 0) reds[tid >> 5] = s;
    __syncthreads();
    s = reds[0];
#pragma unroll
    for (int w = 1; w < 8; w++) s += reds[w];
    float inv = 1.0f / s;
    v.x *= inv; v.y *= inv; v.z *= inv; v.w *= inv;
    ((float4*)x)[tid] = v;
}

// ---------------------------------------------------------------------------
extern "C" void kernel_launch(void* const* d_in, const int* in_sizes, int n_in,
                              void* d_out, int out_size)
{
    const float* q    = (const float*)d_in[0];
    const float* kv   = (const float*)d_in[1];
    const int*   mask = (const int*)d_in[2];
    const float* Wq   = (const float*)d_in[3];
    const float* bq   = (const float*)d_in[4];
    const float* Wk   = (const float*)d_in[5];
    const float* bk   = (const float*)d_in[6];
    const float* Wv   = (const float*)d_in[7];
    const float* bv   = (const float*)d_in[8];
    const float* Wo   = (const float*)d_in[9];
    const float* bo   = (const float*)d_in[10];
    const float* R    = (const float*)d_in[11];

    float* out = (float*)d_out;
    const size_t OUT0_ELEMS = (size_t)B_ * NQ_ * DQ_;
    const size_t ATTN_ELEMS = (size_t)BH_ * NQ_ * NKV_;

    float *Qp, *Kp, *Vp, *Ob, *attn_scr;
    cudaGetSymbolAddress((void**)&Qp, g_Qp);
    cudaGetSymbolAddress((void**)&Kp, g_Kp);
    cudaGetSymbolAddress((void**)&Vp, g_Vp);
    cudaGetSymbolAddress((void**)&Ob, g_Obuf);
    cudaGetSymbolAddress((void**)&attn_scr, g_attn_scratch);

    float* attn = ((size_t)out_size >= OUT0_ELEMS + ATTN_ELEMS) ? (out + OUT0_ELEMS)
                                                                : attn_scr;

    // Projections: [8192,512] @ [512,512] -> scatter [bh, n, 64]  (split bf16)
    mma_gemm<128,128,32,64,32,false,1,3><<<dim3(4,64,1),256>>>(
        q,  Wq, bq, Qp, 512, 512, 512, 0, 0, 0, 0);
    mma_gemm<128,128,32,64,32,false,1,3><<<dim3(4,64,1),256>>>(
        kv, Wk, bk, Kp, 512, 512, 512, 0, 0, 0, 0);
    mma_gemm<128,128,32,64,32,false,1,3><<<dim3(4,64,1),256>>>(
        kv, Wv, bv, Vp, 512, 512, 512, 0, 0, 0, 0);

    // RPE: per-q [64bh x 64d] @ R[q]^T -> raw scores  (single bf16: R ~0.02)
    mma_gemm<64,128,32,32,32,true,0,1><<<dim3(8,1,1024),256>>>(
        Qp, R, nullptr, attn, 64,
        /*lda=*/65536, /*ldb=*/64, /*ldc=*/1048576,
        /*sA=*/64, /*sB=*/65536, /*sC=*/1024);

    // QK^T: batched -> RMW into scores  (split bf16)
    mma_gemm<128,128,32,64,32,true,2,3><<<dim3(8,8,64),256>>>(
        Qp, Kp, nullptr, attn, 64,
        /*lda=*/64, /*ldb=*/64, /*ldc=*/1024,
        /*sA=*/65536, /*sB=*/65536, /*sC=*/1048576);

    // scale + mask + softmax (in place)
    softmax_kernel<<<BH_ * NQ_, 256>>>(attn, mask);

    // AV: batched [1024x1024] @ V[1024x64] -> Obuf  (split bf16)
    mma_gemm<128,64,32,32,32,false,3,3><<<dim3(1,8,64),256>>>(
        attn, Vp, nullptr, Ob, 1024,
        /*lda=*/1024, /*ldb=*/64, /*ldc=*/0,
        /*sA=*/1048576, /*sB=*/65536, /*sC=*/0);

    // Out projection: [8192,512] @ [512,512] -> out  (split bf16)
    mma_gemm<128,128,32,64,32,false,0,3><<<dim3(4,64,1),256>>>(
        Ob, Wo, bo, out, 512, 512, 512, 512, 0, 0, 0);
}

// round 5
// speedup vs baseline: 2.8102x; 1.0830x over previous
#include <cuda_runtime.h>
#include <cstdint>
#include <cstddef>
#include <math.h>

#define B_   8
#define NQ_  1024
#define NKV_ 1024
#define DQ_  512
#define H_   8
#define DH_  64
#define BH_  64

__device__ float g_Qp[BH_ * NQ_ * DH_];       // [bh, q, d]
__device__ float g_Kp[BH_ * NKV_ * DH_];      // [bh, k, d]
__device__ float g_Vp[BH_ * NKV_ * DH_];      // [bh, k, d]
__device__ float g_Obuf[B_ * NQ_ * H_ * DH_]; // [b, q, h*64+d]
__device__ float g_attn_scratch[(size_t)BH_ * NQ_ * NKV_];

// pack two floats into bf16x2: x0 -> low half, x1 -> high half
__device__ __forceinline__ uint32_t packbf(float x0, float x1) {
    uint32_t r;
    asm("cvt.rn.bf16x2.f32 %0, %1, %2;" : "=r"(r) : "f"(x1), "f"(x0));
    return r;
}
__device__ __forceinline__ float bf_lo(uint32_t r) { return __uint_as_float(r << 16); }
__device__ __forceinline__ float bf_hi(uint32_t r) { return __uint_as_float(r & 0xffff0000u); }

__device__ __forceinline__ void mma16(float* c, const uint32_t* a, const uint32_t* b) {
    asm volatile(
        "mma.sync.aligned.m16n8k16.row.col.f32.bf16.bf16.f32 "
        "{%0,%1,%2,%3},{%4,%5,%6,%7},{%8,%9},{%0,%1,%2,%3};"
        : "+f"(c[0]), "+f"(c[1]), "+f"(c[2]), "+f"(c[3])
        : "r"(a[0]), "r"(a[1]), "r"(a[2]), "r"(a[3]), "r"(b[0]), "r"(b[1]));
}

// ---------------------------------------------------------------------------
// Generic GEMM on bf16 tensor cores with split-bf16 accuracy (projections,
// RPE, out-proj).  Same as R4.
// ---------------------------------------------------------------------------
template <int BM, int BN, int BK, int WM, int WN, bool BCOL, int EPI, int NSPLIT>
__global__ __launch_bounds__(256, 1) void mma_gemm(
    const float* __restrict__ A, const float* __restrict__ Bg,
    const float* __restrict__ bias, float* __restrict__ C,
    int K, long lda, long ldb, long ldc, long sA, long sB, long sC)
{
    constexpr int MT = WM / 16, NT = WN / 8;
    constexpr int WX = BN / WN;
    constexpr int KW = BK / 2;
    constexpr bool SPL = (NSPLIT == 3);
    constexpr int BR  = BCOL ? BN : KW;
    constexpr int BCW = BCOL ? (KW + 4) : (BN + 8);

    __shared__ uint32_t sAh[BM][KW + 4];
    __shared__ uint32_t sAl[SPL ? BM : 1][SPL ? KW + 4 : 1];
    __shared__ uint32_t sBh[BR][BCW];
    __shared__ uint32_t sBl[SPL ? BR : 1][SPL ? BCW : 1];

    const int tid = threadIdx.x;
    const int warp = tid >> 5, lane = tid & 31;
    const int wx = warp % WX, wy = warp / WX;
    const long z = blockIdx.z;

    const float* Ab = A + z * sA + (long)blockIdx.y * BM * lda;
    const float* Bb = BCOL ? (Bg + z * sB + (long)blockIdx.x * BN * ldb)
                           : (Bg + z * sB + (long)blockIdx.x * BN);

    float acc[MT * NT][4];
#pragma unroll
    for (int i = 0; i < MT * NT; i++)
#pragma unroll
        for (int r = 0; r < 4; r++) acc[i][r] = 0.0f;

    for (int k0 = 0; k0 < K; k0 += BK) {
        constexpr int AIT = (BM * BK / 4) / 256;
#pragma unroll
        for (int it = 0; it < AIT; it++) {
            int idx = tid + it * 256;
            int m = idx / (BK / 4), kq = idx % (BK / 4);
            float4 v = *(const float4*)(Ab + (long)m * lda + k0 + kq * 4);
            uint32_t h0 = packbf(v.x, v.y), h1 = packbf(v.z, v.w);
            sAh[m][kq * 2] = h0; sAh[m][kq * 2 + 1] = h1;
            if (SPL) {
                sAl[m][kq * 2]     = packbf(v.x - bf_lo(h0), v.y - bf_hi(h0));
                sAl[m][kq * 2 + 1] = packbf(v.z - bf_lo(h1), v.w - bf_hi(h1));
            }
        }
        if (BCOL) {
            constexpr int BIT = (BN * BK / 4) / 256;
#pragma unroll
            for (int it = 0; it < BIT; it++) {
                int idx = tid + it * 256;
                int n = idx / (BK / 4), kq = idx % (BK / 4);
                float4 v = *(const float4*)(Bb + (long)n * ldb + k0 + kq * 4);
                uint32_t h0 = packbf(v.x, v.y), h1 = packbf(v.z, v.w);
                sBh[n][kq * 2] = h0; sBh[n][kq * 2 + 1] = h1;
                if (SPL) {
                    sBl[n][kq * 2]     = packbf(v.x - bf_lo(h0), v.y - bf_hi(h0));
                    sBl[n][kq * 2 + 1] = packbf(v.z - bf_lo(h1), v.w - bf_hi(h1));
                }
            }
        } else {
            constexpr int BIT = (KW * (BN / 4) + 255) / 256;
#pragma unroll
            for (int it = 0; it < BIT; it++) {
                int idx = tid + it * 256;
                if (KW * (BN / 4) % 256 != 0 && idx >= KW * (BN / 4)) break;
                int kp = idx / (BN / 4), n4 = (idx % (BN / 4)) * 4;
                float4 v0 = *(const float4*)(Bb + (long)(k0 + kp * 2) * ldb + n4);
                float4 v1 = *(const float4*)(Bb + (long)(k0 + kp * 2 + 1) * ldb + n4);
                uint32_t h0 = packbf(v0.x, v1.x), h1 = packbf(v0.y, v1.y);
                uint32_t h2 = packbf(v0.z, v1.z), h3 = packbf(v0.w, v1.w);
                sBh[kp][n4 + 0] = h0; sBh[kp][n4 + 1] = h1;
                sBh[kp][n4 + 2] = h2; sBh[kp][n4 + 3] = h3;
                if (SPL) {
                    sBl[kp][n4 + 0] = packbf(v0.x - bf_lo(h0), v1.x - bf_hi(h0));
                    sBl[kp][n4 + 1] = packbf(v0.y - bf_lo(h1), v1.y - bf_hi(h1));
                    sBl[kp][n4 + 2] = packbf(v0.z - bf_lo(h2), v1.z - bf_hi(h2));
                    sBl[kp][n4 + 3] = packbf(v0.w - bf_lo(h3), v1.w - bf_hi(h3));
                }
            }
        }
        __syncthreads();

#pragma unroll
        for (int kc = 0; kc < KW; kc += 8) {
            const int kb = kc + (lane & 3);
            const int mrow = wy * WM + (lane >> 2);
            uint32_t afh[MT][4], afl[MT][4];
#pragma unroll
            for (int i = 0; i < MT; i++) {
                int m = mrow + i * 16;
                afh[i][0] = sAh[m][kb];     afh[i][1] = sAh[m + 8][kb];
                afh[i][2] = sAh[m][kb + 4]; afh[i][3] = sAh[m + 8][kb + 4];
                if (SPL) {
                    afl[i][0] = sAl[m][kb];     afl[i][1] = sAl[m + 8][kb];
                    afl[i][2] = sAl[m][kb + 4]; afl[i][3] = sAl[m + 8][kb + 4];
                }
            }
#pragma unroll
            for (int j = 0; j < NT; j++) {
                uint32_t bfh[2], bfl[2];
                int n = wx * WN + j * 8 + (lane >> 2);
                if (BCOL) {
                    bfh[0] = sBh[n][kb]; bfh[1] = sBh[n][kb + 4];
                    if (SPL) { bfl[0] = sBl[n][kb]; bfl[1] = sBl[n][kb + 4]; }
                } else {
                    bfh[0] = sBh[kb][n]; bfh[1] = sBh[kb + 4][n];
                    if (SPL) { bfl[0] = sBl[kb][n]; bfl[1] = sBl[kb + 4][n]; }
                }
#pragma unroll
                for (int i = 0; i < MT; i++) {
                    mma16(acc[i * NT + j], afh[i], bfh);
                    if (SPL) {
                        mma16(acc[i * NT + j], afh[i], bfl);
                        mma16(acc[i * NT + j], afl[i], bfh);
                    }
                }
            }
        }
        __syncthreads();
    }

    const long m0 = (long)blockIdx.y * BM + wy * WM;
    const long n0 = (long)blockIdx.x * BN + wx * WN;
    float* Cb = C + z * sC;
    long ldcc = ldc;

#pragma unroll
    for (int i = 0; i < MT; i++) {
#pragma unroll
        for (int j = 0; j < NT; j++) {
#pragma unroll
            for (int r2 = 0; r2 < 2; r2++) {
                long row = m0 + i * 16 + r2 * 8 + (lane >> 2);
                long col = n0 + j * 8 + (lane & 3) * 2;
                float v0 = acc[i * NT + j][r2 * 2 + 0];
                float v1 = acc[i * NT + j][r2 * 2 + 1];
                if ((EPI == 0 || EPI == 1) && bias) { v0 += bias[col]; v1 += bias[col + 1]; }
                if (EPI == 1) {
                    long bb = row >> 10, ns = row & 1023;
                    long h = col >> 6, d = col & 63;
                    float* p = C + (((bb * 8 + h) * 1024 + ns) * 64 + d);
                    *(float2*)p = make_float2(v0, v1);
                } else {
                    *(float2*)(Cb + row * ldcc + col) = make_float2(v0, v1);
                }
            }
        }
    }
}

// ---------------------------------------------------------------------------
// Fused attention: S = Q K^T (smem) ; softmax((S + rpe_bias)*scale, mask)
// -> attn gmem + P packed bf16 hi/lo in smem ; O = P V -> Obuf.
// Grid (NQ/32, BH).  256 threads.  attn buffer holds RPE bias on entry.
// ---------------------------------------------------------------------------
#define SMEM_WORDS (32*1028 + 2*32*36 + 2*128*36)

__global__ __launch_bounds__(256, 1) void fused_attn(
    const float* __restrict__ Qp, const float* __restrict__ Kp,
    const float* __restrict__ Vp, const int* __restrict__ mask,
    float* __restrict__ attn, float* __restrict__ Obuf)
{
    extern __shared__ uint32_t sm[];
    float*    S   = (float*)sm;          // [32][1028] fp32 scores
    uint32_t* PS  = sm;                  // P packed: row r hi at r*1028+[0..511], lo at r*1028+514+[0..511]
    uint32_t* Qh  = sm + 32 * 1028;      // [32][36]
    uint32_t* Ql  = Qh + 32 * 36;
    uint32_t* KVh = Ql + 32 * 36;        // K: [128][36] / V: [64][68]
    uint32_t* KVl = KVh + 128 * 36;

    const int tid = threadIdx.x, warp = tid >> 5, lane = tid & 31;
    const int q0 = blockIdx.x * 32, bh = blockIdx.y;
    const int b = bh >> 3, h = bh & 7;

    const float* Qb = Qp + bh * 65536 + q0 * 64;
    const float* Kb = Kp + bh * 65536;
    const float* Vb = Vp + bh * 65536;
    float* attnb = attn + (size_t)bh * 1048576 + (size_t)q0 * 1024;

    // ---- stage Q (bf16 hi/lo) ----
#pragma unroll
    for (int t = 0; t < 2; t++) {
        int f = tid + t * 256;
        int m = f >> 4, kq = f & 15;
        float4 v = *(const float4*)(Qb + m * 64 + kq * 4);
        uint32_t h0 = packbf(v.x, v.y), h1 = packbf(v.z, v.w);
        Qh[m * 36 + kq * 2] = h0; Qh[m * 36 + kq * 2 + 1] = h1;
        Ql[m * 36 + kq * 2]     = packbf(v.x - bf_lo(h0), v.y - bf_hi(h0));
        Ql[m * 36 + kq * 2 + 1] = packbf(v.z - bf_lo(h1), v.w - bf_hi(h1));
    }
    __syncthreads();

    // ---- phase 1: S = Q K^T (split bf16), K streamed in 128-k tiles ----
    for (int kt = 0; kt < 8; kt++) {
#pragma unroll
        for (int t = 0; t < 8; t++) {
            int f = tid + t * 256;
            int r = f >> 4, kq = f & 15;
            float4 v = *(const float4*)(Kb + (kt * 128 + r) * 64 + kq * 4);
            uint32_t h0 = packbf(v.x, v.y), h1 = packbf(v.z, v.w);
            KVh[r * 36 + kq * 2] = h0; KVh[r * 36 + kq * 2 + 1] = h1;
            KVl[r * 36 + kq * 2]     = packbf(v.x - bf_lo(h0), v.y - bf_hi(h0));
            KVl[r * 36 + kq * 2 + 1] = packbf(v.z - bf_lo(h1), v.w - bf_hi(h1));
        }
        __syncthreads();
        float acc[2][2][4] = {};
#pragma unroll
        for (int c = 0; c < 4; c++) {
            int kb = c * 8 + (lane & 3);
            uint32_t ah[2][4], al[2][4];
#pragma unroll
            for (int mi = 0; mi < 2; mi++) {
                int m = mi * 16 + (lane >> 2);
                ah[mi][0] = Qh[m * 36 + kb];       ah[mi][1] = Qh[(m + 8) * 36 + kb];
                ah[mi][2] = Qh[m * 36 + kb + 4];   ah[mi][3] = Qh[(m + 8) * 36 + kb + 4];
                al[mi][0] = Ql[m * 36 + kb];       al[mi][1] = Ql[(m + 8) * 36 + kb];
                al[mi][2] = Ql[m * 36 + kb + 4];   al[mi][3] = Ql[(m + 8) * 36 + kb + 4];
            }
#pragma unroll
            for (int nj = 0; nj < 2; nj++) {
                int n = warp * 16 + nj * 8 + (lane >> 2);
                uint32_t bfh[2] = { KVh[n * 36 + kb], KVh[n * 36 + kb + 4] };
                uint32_t bfl[2] = { KVl[n * 36 + kb], KVl[n * 36 + kb + 4] };
#pragma unroll
                for (int mi = 0; mi < 2; mi++) {
                    mma16(acc[mi][nj], ah[mi], bfh);
                    mma16(acc[mi][nj], ah[mi], bfl);
                    mma16(acc[mi][nj], al[mi], bfh);
                }
            }
        }
#pragma unroll
        for (int mi = 0; mi < 2; mi++)
#pragma unroll
            for (int nj = 0; nj < 2; nj++) {
                int r = mi * 16 + (lane >> 2);
                int cc = kt * 128 + warp * 16 + nj * 8 + (lane & 3) * 2;
                *(float2*)&S[r * 1028 + cc]       = make_float2(acc[mi][nj][0], acc[mi][nj][1]);
                *(float2*)&S[(r + 8) * 1028 + cc] = make_float2(acc[mi][nj][2], acc[mi][nj][3]);
            }
        __syncthreads();
    }

    // ---- phase 2: softmax((S + bias)*scale, mask) -> attn gmem + packed P ----
    const int4* mrow = (const int4*)(mask + b * 1024);
    for (int rr = 0; rr < 4; rr++) {
        int r = warp * 4 + rr;
        float4 v[8];
        float mx = -INFINITY;
#pragma unroll
        for (int j = 0; j < 8; j++) {
            int c4 = lane + j * 32;
            float4 s4 = *(float4*)&S[r * 1028 + c4 * 4];
            float4 bb = *(const float4*)(attnb + r * 1024 + c4 * 4);
            int4 mm = mrow[c4];
            s4.x = mm.x ? (s4.x + bb.x) * 0.125f : -INFINITY;
            s4.y = mm.y ? (s4.y + bb.y) * 0.125f : -INFINITY;
            s4.z = mm.z ? (s4.z + bb.z) * 0.125f : -INFINITY;
            s4.w = mm.w ? (s4.w + bb.w) * 0.125f : -INFINITY;
            v[j] = s4;
            mx = fmaxf(mx, fmaxf(fmaxf(s4.x, s4.y), fmaxf(s4.z, s4.w)));
        }
#pragma unroll
        for (int o = 16; o; o >>= 1) mx = fmaxf(mx, __shfl_xor_sync(0xffffffffu, mx, o));
        float sum = 0.0f;
#pragma unroll
        for (int j = 0; j < 8; j++) {
            v[j].x = __expf(v[j].x - mx); v[j].y = __expf(v[j].y - mx);
            v[j].z = __expf(v[j].z - mx); v[j].w = __expf(v[j].w - mx);
            sum += v[j].x + v[j].y + v[j].z + v[j].w;
        }
#pragma unroll
        for (int o = 16; o; o >>= 1) sum += __shfl_xor_sync(0xffffffffu, sum, o);
        float inv = 1.0f / sum;
#pragma unroll
        for (int j = 0; j < 8; j++) {
            v[j].x *= inv; v[j].y *= inv; v[j].z *= inv; v[j].w *= inv;
            int c4 = lane + j * 32;
            *(float4*)(attnb + r * 1024 + c4 * 4) = v[j];
            uint32_t h0 = packbf(v[j].x, v[j].y), h1 = packbf(v[j].z, v[j].w);
            PS[r * 1028 + c4 * 2]     = h0;
            PS[r * 1028 + c4 * 2 + 1] = h1;
            PS[r * 1028 + 514 + c4 * 2]     = packbf(v[j].x - bf_lo(h0), v[j].y - bf_hi(h0));
            PS[r * 1028 + 514 + c4 * 2 + 1] = packbf(v[j].z - bf_lo(h1), v[j].w - bf_hi(h1));
        }
    }
    __syncthreads();

    // ---- phase 3: O = P V (split bf16), V streamed in 128-k tiles ----
    float accO[2][4] = {};
    for (int kt = 0; kt < 8; kt++) {
#pragma unroll
        for (int t = 0; t < 4; t++) {
            int f = tid + t * 256;
            int p = f >> 4, d4 = (f & 15) * 4;
            const float* vp0 = Vb + (kt * 128 + 2 * p) * 64 + d4;
            float4 v0 = *(const float4*)vp0;
            float4 v1 = *(const float4*)(vp0 + 64);
            uint32_t w0 = packbf(v0.x, v1.x), w1 = packbf(v0.y, v1.y);
            uint32_t w2 = packbf(v0.z, v1.z), w3 = packbf(v0.w, v1.w);
            KVh[(d4 + 0) * 68 + p] = w0; KVh[(d4 + 1) * 68 + p] = w1;
            KVh[(d4 + 2) * 68 + p] = w2; KVh[(d4 + 3) * 68 + p] = w3;
            KVl[(d4 + 0) * 68 + p] = packbf(v0.x - bf_lo(w0), v1.x - bf_hi(w0));
            KVl[(d4 + 1) * 68 + p] = packbf(v0.y - bf_lo(w1), v1.y - bf_hi(w1));
            KVl[(d4 + 2) * 68 + p] = packbf(v0.z - bf_lo(w2), v1.z - bf_hi(w2));
            KVl[(d4 + 3) * 68 + p] = packbf(v0.w - bf_lo(w3), v1.w - bf_hi(w3));
        }
        __syncthreads();
#pragma unroll
        for (int c = 0; c < 8; c++) {
            int kb = c * 8 + (lane & 3);
            int gk = kt * 64 + kb;
            uint32_t ah[2][4], al[2][4];
#pragma unroll
            for (int mi = 0; mi < 2; mi++) {
                int m = mi * 16 + (lane >> 2);
                ah[mi][0] = PS[m * 1028 + gk];           ah[mi][1] = PS[(m + 8) * 1028 + gk];
                ah[mi][2] = PS[m * 1028 + gk + 4];       ah[mi][3] = PS[(m + 8) * 1028 + gk + 4];
                al[mi][0] = PS[m * 1028 + 514 + gk];     al[mi][1] = PS[(m + 8) * 1028 + 514 + gk];
                al[mi][2] = PS[m * 1028 + 514 + gk + 4]; al[mi][3] = PS[(m + 8) * 1028 + 514 + gk + 4];
            }
            int n = warp * 8 + (lane >> 2);
            uint32_t bvh[2] = { KVh[n * 68 + kb], KVh[n * 68 + kb + 4] };
            uint32_t bvl[2] = { KVl[n * 68 + kb], KVl[n * 68 + kb + 4] };
#pragma unroll
            for (int mi = 0; mi < 2; mi++) {
                mma16(accO[mi], ah[mi], bvh);
                mma16(accO[mi], ah[mi], bvl);
                mma16(accO[mi], al[mi], bvh);
            }
        }
        __syncthreads();
    }
    // epilogue -> Obuf [b, q, h*64+d]
#pragma unroll
    for (int mi = 0; mi < 2; mi++) {
        int r0 = q0 + mi * 16 + (lane >> 2);
        int col = h * 64 + warp * 8 + (lane & 3) * 2;
        *(float2*)&Obuf[(size_t)(b * 1024 + r0) * 512 + col]       = make_float2(accO[mi][0], accO[mi][1]);
        *(float2*)&Obuf[(size_t)(b * 1024 + r0 + 8) * 512 + col]   = make_float2(accO[mi][2], accO[mi][3]);
    }
}

// ---------------------------------------------------------------------------
extern "C" void kernel_launch(void* const* d_in, const int* in_sizes, int n_in,
                              void* d_out, int out_size)
{
    const float* q    = (const float*)d_in[0];
    const float* kv   = (const float*)d_in[1];
    const int*   mask = (const int*)d_in[2];
    const float* Wq   = (const float*)d_in[3];
    const float* bq   = (const float*)d_in[4];
    const float* Wk   = (const float*)d_in[5];
    const float* bk   = (const float*)d_in[6];
    const float* Wv   = (const float*)d_in[7];
    const float* bv   = (const float*)d_in[8];
    const float* Wo   = (const float*)d_in[9];
    const float* bo   = (const float*)d_in[10];
    const float* R    = (const float*)d_in[11];

    float* out = (float*)d_out;
    const size_t OUT0_ELEMS = (size_t)B_ * NQ_ * DQ_;
    const size_t ATTN_ELEMS = (size_t)BH_ * NQ_ * NKV_;

    float *Qp, *Kp, *Vp, *Ob, *attn_scr;
    cudaGetSymbolAddress((void**)&Qp, g_Qp);
    cudaGetSymbolAddress((void**)&Kp, g_Kp);
    cudaGetSymbolAddress((void**)&Vp, g_Vp);
    cudaGetSymbolAddress((void**)&Ob, g_Obuf);
    cudaGetSymbolAddress((void**)&attn_scr, g_attn_scratch);

    float* attn = ((size_t)out_size >= OUT0_ELEMS + ATTN_ELEMS) ? (out + OUT0_ELEMS)
                                                                : attn_scr;

    static int smem_set = 0;
    if (!smem_set) {
        cudaFuncSetAttribute(fused_attn, cudaFuncAttributeMaxDynamicSharedMemorySize,
                             SMEM_WORDS * 4);
        smem_set = 1;
    }

    // Projections -> scatter [bh, n, 64]  (split bf16)
    mma_gemm<128,128,32,64,32,false,1,3><<<dim3(4,64,1),256>>>(
        q,  Wq, bq, Qp, 512, 512, 512, 0, 0, 0, 0);
    mma_gemm<128,128,32,64,32,false,1,3><<<dim3(4,64,1),256>>>(
        kv, Wk, bk, Kp, 512, 512, 512, 0, 0, 0, 0);
    mma_gemm<128,128,32,64,32,false,1,3><<<dim3(4,64,1),256>>>(
        kv, Wv, bv, Vp, 512, 512, 512, 0, 0, 0, 0);

    // RPE bias: per-q [64bh x 64d] @ R[q]^T -> raw bias into attn (single bf16)
    mma_gemm<64,128,32,32,32,true,0,1><<<dim3(8,1,1024),256>>>(
        Qp, R, nullptr, attn, 64,
        /*lda=*/65536, /*ldb=*/64, /*ldc=*/1048576,
        /*sA=*/64, /*sB=*/65536, /*sC=*/1024);

    // Fused QK^T + bias + mask/scale + softmax + AV
    fused_attn<<<dim3(NQ_/32, BH_), 256, SMEM_WORDS * 4>>>(
        Qp, Kp, Vp, mask, attn, Ob);

    // Out projection
    mma_gemm<128,128,32,64,32,false,0,3><<<dim3(4,64,1),256>>>(
        Ob, Wo, bo, out, 512, 512, 512, 512, 0, 0, 0);
}